// round 7
// baseline (speedup 1.0000x reference)
#include <cuda_runtime.h>
#include <cuda_fp16.h>
#include <math.h>

#define NN 500000
#define TN (2 * NN)
#define T 256
#define RB 592
#define SCAN_B 1024
#define NBLK ((TN + SCAN_B - 1) / SCAN_B)   // 977
#define MAXE 16400000

// ---------------- static device scratch ----------------
// g_zf: deg(2NN) | nrm(2NN) | s2(2NN) | ns(2NN float2) = 10NN floats; only deg needs zeroing
__device__ __align__(16) float g_zf[10UL * NN];
__device__ __align__(16) __half g_q1[16UL * NN];   // 2NN rows x 8 halves (lane7 = norm^2)
__device__ __align__(16) __half g_h1[16UL * NN];   // 2NN rows (lane7 = norm)
__device__ __align__(16) __half g_x2[16UL * NN];
__device__ int g_rs[TN];        // CSR row start
__device__ int g_cur[TN];       // scatter cursors
__device__ int g_csr[MAXE];     // src (+graph offset), grouped by dst
__device__ int g_bsum[SCAN_B], g_boff[SCAN_B];
__device__ double g_stats[2][32];
__device__ float  g_coef[2][64];

#define DEGF (g_zf)
#define NRMF (g_zf + 2UL * NN)
#define S2F  (g_zf + 4UL * NN)
#define NSF  ((float2*)(g_zf + 6UL * NN))
#define Q1R  ((uint4*)g_q1)
#define H1R  ((uint4*)g_h1)
#define X2R  ((uint4*)g_x2)

// ---------------- helpers ----------------
template <int K>
__device__ __forceinline__ void block_reduce_add(double* vals, double* out) {
    __shared__ double sm[K][33];
    int lane = threadIdx.x & 31, wid = threadIdx.x >> 5;
#pragma unroll
    for (int k = 0; k < K; k++) {
        double v = vals[k];
#pragma unroll
        for (int o = 16; o; o >>= 1) v += __shfl_down_sync(0xffffffffu, v, o);
        if (lane == 0) sm[k][wid] = v;
    }
    __syncthreads();
    int nw = blockDim.x >> 5;
    if (wid == 0) {
#pragma unroll
        for (int k = 0; k < K; k++) {
            double v = (lane < nw) ? sm[k][lane] : 0.0;
#pragma unroll
            for (int o = 16; o; o >>= 1) v += __shfl_down_sync(0xffffffffu, v, o);
            if (lane == 0) atomicAdd(&out[k], v);
        }
    }
}

__device__ __forceinline__ unsigned h2u(__half2 v) { return *reinterpret_cast<unsigned*>(&v); }

// accumulate 7 lanes of a gathered row into fp32 acc, weighted by lane7
__device__ __forceinline__ void acc_row(uint4 r, float* a) {
    __half2 p01 = *(__half2*)&r.x, p23 = *(__half2*)&r.y;
    __half2 p45 = *(__half2*)&r.z, p67 = *(__half2*)&r.w;
    float2 t67 = __half22float2(p67);
    float w = t67.y;
    float2 t01 = __half22float2(p01), t23 = __half22float2(p23), t45 = __half22float2(p45);
    a[0] += w * t01.x; a[1] += w * t01.y;
    a[2] += w * t23.x; a[3] += w * t23.y;
    a[4] += w * t45.x; a[5] += w * t45.y;
    a[6] += w * t67.x;
}

// ---------------- kernels ----------------
__global__ void k_zero() {
    size_t tid = (size_t)blockIdx.x * blockDim.x + threadIdx.x;
    size_t stride = (size_t)gridDim.x * blockDim.x;
    for (size_t k = tid; k < TN / 4; k += stride) ((float4*)DEGF)[k] = make_float4(0.f, 0.f, 0.f, 0.f);
    if (tid < 64) ((double*)g_stats)[tid] = 0.0;
}

__global__ void k_deg(const int* __restrict__ d0, const int* __restrict__ d1,
                      int E0, int E1, int nb0) {
    int b = blockIdx.x, off = 0;
    const int* dst; int E;
    if (b < nb0) { dst = d0; E = E0; }
    else { b -= nb0; dst = d1; E = E1; off = NN; }
    int base = (b * blockDim.x + threadIdx.x) * 4;
    if (base + 3 < E) {
        int4 d = *(const int4*)(dst + base);
        atomicAdd(&DEGF[d.x + off], 1.f); atomicAdd(&DEGF[d.y + off], 1.f);
        atomicAdd(&DEGF[d.z + off], 1.f); atomicAdd(&DEGF[d.w + off], 1.f);
    } else {
        for (int e = base; e < E; e++) atomicAdd(&DEGF[dst[e] + off], 1.f);
    }
}

__global__ void k_scanA() {
    __shared__ int sm[32];
    int i = blockIdx.x * SCAN_B + threadIdx.x;
    int lane = threadIdx.x & 31, wid = threadIdx.x >> 5;
    int v = (i < TN) ? (int)DEGF[i] : 0;
#pragma unroll
    for (int o = 16; o; o >>= 1) v += __shfl_down_sync(0xffffffffu, v, o);
    if (lane == 0) sm[wid] = v;
    __syncthreads();
    if (wid == 0) {
        v = (lane < SCAN_B / 32) ? sm[lane] : 0;
#pragma unroll
        for (int o = 16; o; o >>= 1) v += __shfl_down_sync(0xffffffffu, v, o);
        if (lane == 0) g_bsum[blockIdx.x] = v;
    }
}

__global__ void k_scanB() {
    __shared__ int sm[SCAN_B];
    int tid = threadIdx.x;
    int v = (tid < NBLK) ? g_bsum[tid] : 0;
    sm[tid] = v;
    __syncthreads();
    for (int o = 1; o < SCAN_B; o <<= 1) {
        int t = (tid >= o) ? sm[tid - o] : 0;
        __syncthreads();
        sm[tid] += t;
        __syncthreads();
    }
    g_boff[tid] = sm[tid] - v;   // exclusive
}

__global__ void k_scanC() {
    __shared__ int sm[SCAN_B];
    int tid = threadIdx.x;
    int i = blockIdx.x * SCAN_B + tid;
    float dgf = (i < TN) ? DEGF[i] : 0.f;
    int d = (int)dgf;
    sm[tid] = d;
    __syncthreads();
    for (int o = 1; o < SCAN_B; o <<= 1) {
        int t = (tid >= o) ? sm[tid - o] : 0;
        __syncthreads();
        sm[tid] += t;
        __syncthreads();
    }
    if (i < TN) {
        int rs = g_boff[blockIdx.x] + sm[tid] - d;
        g_rs[i] = rs;
        g_cur[i] = rs;
        NRMF[i] = rsqrtf(fmaxf(dgf, 1.0f));
    }
}

__global__ void k_scatter(const int* __restrict__ s0, const int* __restrict__ d0,
                          const int* __restrict__ s1, const int* __restrict__ d1,
                          int E0, int E1, int nb0) {
    int b = blockIdx.x, off = 0;
    const int *src, *dst; int E;
    if (b < nb0) { src = s0; dst = d0; E = E0; }
    else { b -= nb0; src = s1; dst = d1; E = E1; off = NN; }
    int base = (b * blockDim.x + threadIdx.x) * 4;
    if (base + 3 < E) {
        int4 s = *(const int4*)(src + base);
        int4 d = *(const int4*)(dst + base);
        int p0 = atomicAdd(&g_cur[d.x + off], 1);
        int p1 = atomicAdd(&g_cur[d.y + off], 1);
        int p2 = atomicAdd(&g_cur[d.z + off], 1);
        int p3 = atomicAdd(&g_cur[d.w + off], 1);
        g_csr[p0] = s.x + off; g_csr[p1] = s.y + off;
        g_csr[p2] = s.z + off; g_csr[p3] = s.w + off;
    } else {
        for (int e = base; e < E; e++) {
            int p = atomicAdd(&g_cur[dst[e] + off], 1);
            g_csr[p] = src[e] + off;
        }
    }
}

// s1[i] = sum over in-edges of norm[src]; write ns = {norm, s1}
__global__ void k_p1csr() {
    int i = blockIdx.x * blockDim.x + threadIdx.x;
    if (i >= TN) return;
    int rs = g_rs[i], dg = (int)DEGF[i];
    int e = rs, end = rs + dg;
    float s = 0.f;
    for (; e + 3 < end; e += 4) {
        int c0 = g_csr[e], c1 = g_csr[e + 1], c2 = g_csr[e + 2], c3 = g_csr[e + 3];
        float w0 = __ldg(&NRMF[c0]), w1 = __ldg(&NRMF[c1]);
        float w2 = __ldg(&NRMF[c2]), w3 = __ldg(&NRMF[c3]);
        s += (w0 + w1) + (w2 + w3);
    }
    for (; e < end; e++) s += __ldg(&NRMF[g_csr[e]]);
    NSF[i] = make_float2(NRMF[i], s);
}

// s2[i] = sum of norm^2*s1 over in-edges; also layer-1 stats (5 moments per graph)
__global__ void k_p2csr(int nbg) {
    int g = blockIdx.x < nbg ? 0 : 1;
    int b = g ? blockIdx.x - nbg : blockIdx.x;
    int i = b * blockDim.x + threadIdx.x;
    double acc[5] = {0, 0, 0, 0, 0};
    if (i < NN) {
        i += g * NN;
        int rs = g_rs[i], dg = (int)DEGF[i];
        int e = rs, end = rs + dg;
        float s = 0.f;
        for (; e + 1 < end; e += 2) {
            float2 v0 = __ldg(&NSF[g_csr[e]]);
            float2 v1 = __ldg(&NSF[g_csr[e + 1]]);
            s += v0.x * v0.x * v0.y + v1.x * v1.x * v1.y;
        }
        for (; e < end; e++) {
            float2 v = __ldg(&NSF[g_csr[e]]);
            s += v.x * v.x * v.y;
        }
        S2F[i] = s;
        float2 me = NSF[i];
        float p1 = me.x * me.y, p2 = me.x * s;
        acc[0] = p1; acc[1] = p2;
        acc[2] = (double)p1 * p1; acc[3] = (double)p2 * p2; acc[4] = (double)p1 * p2;
    }
    block_reduce_add<5>(acc, g_stats[g]);
}

__global__ void k_coef1(const float* __restrict__ W_init, const float* __restrict__ b_init,
                        const float* __restrict__ Wg, const float* __restrict__ bg,
                        const float* __restrict__ Wt1, const float* __restrict__ g1,
                        const float* __restrict__ b1) {
    int g = blockIdx.x;
    if (threadIdx.x != 0) return;
    float xrow[4];
    for (int j = 0; j < 4; j++) {
        float s = b_init[j];
        for (int i = 0; i < 12; i++) s += W_init[i * 4 + j];
        xrow[j] = s;
    }
    float hrow[7];
    for (int k = 0; k < 7; k++) {
        float s = bg[k];
        for (int j = 0; j < 4; j++) s += xrow[j] * Wg[j * 7 + k];
        hrow[k] = 1.0f / (1.0f + expf(-s));
    }
    const double inv_n = 1.0 / (double)NN;
    double m1 = g_stats[g][0] * inv_n, m2 = g_stats[g][1] * inv_n;
    double v1 = g_stats[g][2] * inv_n - m1 * m1;
    double v2 = g_stats[g][3] * inv_n - m2 * m2;
    double c12 = g_stats[g][4] * inv_n - m1 * m2;
    for (int j = 0; j < 7; j++) {
        float a = 0.f, b = 0.f, c = 0.f;
        for (int k = 0; k < 7; k++) {
            a += hrow[k] * Wt1[k * 7 + j];
            b += hrow[k] * Wt1[(7 + k) * 7 + j];
            c += hrow[k] * Wt1[(14 + k) * 7 + j];
        }
        double mean = (double)a + m1 * (double)b + m2 * (double)c;
        double var = (double)b * b * v1 + (double)c * c * v2 + 2.0 * (double)b * c * c12;
        double sc = (double)g1[j] / sqrt(var + 1e-5);
        g_coef[g][j]      = (float)(((double)a - mean) * sc + (double)b1[j]);
        g_coef[g][8 + j]  = (float)((double)b * sc);
        g_coef[g][16 + j] = (float)((double)c * sc);
    }
}

__global__ void k_h1() {
    __shared__ float cf[2][24];
    if (threadIdx.x < 48) {
        int g = threadIdx.x / 24, j = threadIdx.x % 24;
        cf[g][j] = g_coef[g][(j / 7) * 8 + (j % 7)];
    }
    __syncthreads();
    int i = blockIdx.x * blockDim.x + threadIdx.x;
    if (i >= TN) return;
    int g = i >= NN;
    float2 v = NSF[i];
    float p1 = v.x * v.y, p2 = v.x * S2F[i];
    const float* c = cf[g];
    float o[7];
#pragma unroll
    for (int j = 0; j < 7; j++)
        o[j] = fmaxf(c[j] + p1 * c[7 + j] + p2 * c[14 + j], 0.f);
    __half2 h01 = __floats2half2_rn(o[0], o[1]);
    __half2 h23 = __floats2half2_rn(o[2], o[3]);
    __half2 h45 = __floats2half2_rn(o[4], o[5]);
    __half2 h67 = __floats2half2_rn(o[6], v.x);   // lane7 = norm (prop-1 weight)
    H1R[i] = make_uint4(h2u(h01), h2u(h23), h2u(h45), h2u(h67));
}

// q1[i] = sum of norm[src]*h1[src]; write row, lane7 = norm[i]^2 (prop-2 weight)
__global__ void k_q1csr() {
    int i = blockIdx.x * blockDim.x + threadIdx.x;
    if (i >= TN) return;
    int rs = g_rs[i], dg = (int)DEGF[i];
    float a[7] = {0.f, 0.f, 0.f, 0.f, 0.f, 0.f, 0.f};
    int e = rs, end = rs + dg;
    for (; e + 1 < end; e += 2) {
        uint4 r0 = __ldg(H1R + g_csr[e]);
        uint4 r1 = __ldg(H1R + g_csr[e + 1]);
        acc_row(r0, a);
        acc_row(r1, a);
    }
    for (; e < end; e++) acc_row(__ldg(H1R + g_csr[e]), a);
    float nn = NRMF[i];
    __half2 h01 = __floats2half2_rn(a[0], a[1]);
    __half2 h23 = __floats2half2_rn(a[2], a[3]);
    __half2 h45 = __floats2half2_rn(a[4], a[5]);
    __half2 h67 = __floats2half2_rn(a[6], nn * nn);
    Q1R[i] = make_uint4(h2u(h01), h2u(h23), h2u(h45), h2u(h67));
}

// q2 in registers + TAGConv2 linear + x2 write + BN2 stats
__global__ void k_q2F(const float* __restrict__ Wt2, int nbg) {
    __shared__ float w[147];
    for (int k = threadIdx.x; k < 147; k += blockDim.x) w[k] = Wt2[k];
    __syncthreads();
    int g = blockIdx.x < nbg ? 0 : 1;
    int b = g ? blockIdx.x - nbg : blockIdx.x;
    int i = b * blockDim.x + threadIdx.x;
    double acc[14];
#pragma unroll
    for (int k = 0; k < 14; k++) acc[k] = 0.0;
    if (i < NN) {
        i += g * NN;
        int rs = g_rs[i], dg = (int)DEGF[i];
        float qa[7] = {0.f, 0.f, 0.f, 0.f, 0.f, 0.f, 0.f};
        int e = rs, end = rs + dg;
        for (; e + 1 < end; e += 2) {
            uint4 r0 = __ldg(Q1R + g_csr[e]);
            uint4 r1 = __ldg(Q1R + g_csr[e + 1]);
            acc_row(r0, qa);
            acc_row(r1, qa);
        }
        for (; e < end; e++) acc_row(__ldg(Q1R + g_csr[e]), qa);
        float nn = NRMF[i];
        uint4 hr = H1R[i], ar = Q1R[i];
        float v[21];
        {
            float2 t;
            t = __half22float2(*(__half2*)&hr.x); v[0] = t.x; v[1] = t.y;
            t = __half22float2(*(__half2*)&hr.y); v[2] = t.x; v[3] = t.y;
            t = __half22float2(*(__half2*)&hr.z); v[4] = t.x; v[5] = t.y;
            t = __half22float2(*(__half2*)&hr.w); v[6] = t.x;
            t = __half22float2(*(__half2*)&ar.x); v[7] = nn * t.x; v[8] = nn * t.y;
            t = __half22float2(*(__half2*)&ar.y); v[9] = nn * t.x; v[10] = nn * t.y;
            t = __half22float2(*(__half2*)&ar.z); v[11] = nn * t.x; v[12] = nn * t.y;
            t = __half22float2(*(__half2*)&ar.w); v[13] = nn * t.x;
#pragma unroll
            for (int j = 0; j < 7; j++) v[14 + j] = nn * qa[j];
        }
        float xr[7];
#pragma unroll
        for (int j = 0; j < 7; j++) {
            float s = 0.f;
#pragma unroll
            for (int k = 0; k < 21; k++) s += v[k] * w[k * 7 + j];
            xr[j] = s;
        }
        __half2 x01 = __floats2half2_rn(xr[0], xr[1]);
        __half2 x23 = __floats2half2_rn(xr[2], xr[3]);
        __half2 x45 = __floats2half2_rn(xr[4], xr[5]);
        __half2 x67 = __floats2half2_rn(xr[6], 0.f);
        X2R[i] = make_uint4(h2u(x01), h2u(x23), h2u(x45), h2u(x67));
#pragma unroll
        for (int j = 0; j < 7; j++) {
            acc[j] = xr[j];
            acc[7 + j] = (double)xr[j] * xr[j];
        }
    }
    block_reduce_add<14>(acc, g_stats[g] + 5);
}

__global__ void k_coef2(const float* __restrict__ g2, const float* __restrict__ b2) {
    int g = blockIdx.x;
    if (threadIdx.x != 0) return;
    const double inv_n = 1.0 / (double)NN;
    for (int j = 0; j < 7; j++) {
        double mean = g_stats[g][5 + j] * inv_n;
        double var = g_stats[g][12 + j] * inv_n - mean * mean;
        double sc = (double)g2[j] / sqrt(var + 1e-5);
        g_coef[g][24 + j] = (float)sc;
        g_coef[g][32 + j] = (float)((double)b2[j] - mean * sc);
    }
}

__global__ void k_passG(int nb0) {
    __shared__ float sc[2][7], sh[2][7];
    if (threadIdx.x < 28) {
        int g = threadIdx.x / 14, j = threadIdx.x % 14;
        if (j < 7) sc[g][j] = g_coef[g][24 + j];
        else sh[g][j - 7] = g_coef[g][32 + j - 7];
    }
    __syncthreads();
    int g = blockIdx.x < nb0 ? 0 : 1;
    int b = g ? blockIdx.x - nb0 : blockIdx.x;
    int off = g * NN;
    double acc[7] = {0, 0, 0, 0, 0, 0, 0};
    int stride = nb0 * blockDim.x;
    for (int i = b * blockDim.x + threadIdx.x; i < NN; i += stride) {
        uint4 xr = X2R[i + off];
        float v[7];
        float2 t;
        t = __half22float2(*(__half2*)&xr.x); v[0] = t.x; v[1] = t.y;
        t = __half22float2(*(__half2*)&xr.y); v[2] = t.x; v[3] = t.y;
        t = __half22float2(*(__half2*)&xr.z); v[4] = t.x; v[5] = t.y;
        t = __half22float2(*(__half2*)&xr.w); v[6] = t.x;
#pragma unroll
        for (int j = 0; j < 7; j++)
            acc[j] += fmaxf(v[j] * sc[g][j] + sh[g][j], 0.f);
    }
    block_reduce_add<7>(acc, g_stats[g] + 19);
}

__global__ void k_fin(const float* __restrict__ Wd, const float* __restrict__ bd,
                      const float* __restrict__ Ws0, const float* __restrict__ bs0,
                      const float* __restrict__ Ws1, const float* __restrict__ bs1,
                      const float* __restrict__ Ws2, const float* __restrict__ bs2,
                      const float* __restrict__ Ws3, const float* __restrict__ bs3,
                      const float* __restrict__ Wsim, const float* __restrict__ bsim,
                      float* __restrict__ out) {
    if (threadIdx.x != 0) return;
    const double inv_n = 1.0 / (double)NN;
    float h[22];
    for (int g = 0; g < 2; g++)
        for (int m = 0; m < 11; m++) {
            double s = (double)bd[m];
            for (int j = 0; j < 7; j++)
                s += (g_stats[g][19 + j] * inv_n) * (double)Wd[j * 11 + m];
            h[g * 11 + m] = (float)s;
        }
    float t[7], u[7];
    for (int j = 0; j < 7; j++) {
        float s = bs0[j];
        for (int k = 0; k < 22; k++) s += h[k] * Ws0[k * 7 + j];
        t[j] = s;
    }
    for (int j = 0; j < 7; j++) {
        float s = bs1[j];
        for (int k = 0; k < 7; k++) s += t[k] * Ws1[k * 7 + j];
        u[j] = fmaxf(s, 0.f);
    }
    for (int j = 0; j < 7; j++) {
        float s = bs2[j];
        for (int k = 0; k < 7; k++) s += u[k] * Ws2[k * 7 + j];
        t[j] = fmaxf(s, 0.f);
    }
    for (int j = 0; j < 7; j++) {
        float s = bs3[j];
        for (int k = 0; k < 7; k++) s += t[k] * Ws3[k * 7 + j];
        u[j] = fmaxf(s, 0.f);
    }
    for (int m = 0; m < 12; m++) {
        float s = bsim[m];
        for (int j = 0; j < 7; j++) s += u[j] * Wsim[j * 12 + m];
        out[m] = 1.0f / (1.0f + expf(-s));
    }
}

// ---------------- launch ----------------
extern "C" void kernel_launch(void* const* d_in, const int* in_sizes, int n_in,
                              void* d_out, int out_size) {
    const int* src0 = (const int*)d_in[0];
    const int* dst0 = (const int*)d_in[1];
    const int* src1 = (const int*)d_in[2];
    const int* dst1 = (const int*)d_in[3];
    const float* W_init = (const float*)d_in[5];
    const float* b_init = (const float*)d_in[6];
    const float* Wg  = (const float*)d_in[7];
    const float* bg  = (const float*)d_in[8];
    const float* Wt1 = (const float*)d_in[9];
    const float* g1  = (const float*)d_in[10];
    const float* b1  = (const float*)d_in[11];
    const float* Wt2 = (const float*)d_in[12];
    const float* g2  = (const float*)d_in[13];
    const float* b2  = (const float*)d_in[14];
    const float* Wd  = (const float*)d_in[15];
    const float* bd  = (const float*)d_in[16];
    const float* Ws0 = (const float*)d_in[17];
    const float* bs0 = (const float*)d_in[18];
    const float* Ws1 = (const float*)d_in[19];
    const float* bs1 = (const float*)d_in[20];
    const float* Ws2 = (const float*)d_in[21];
    const float* bs2 = (const float*)d_in[22];
    const float* Ws3 = (const float*)d_in[23];
    const float* bs3 = (const float*)d_in[24];
    const float* Wsim = (const float*)d_in[25];
    const float* bsim = (const float*)d_in[26];

    const int E0 = in_sizes[0];
    const int E1 = in_sizes[2];
    const int eb0_4 = (E0 + T * 4 - 1) / (T * 4);
    const int eb1_4 = (E1 + T * 4 - 1) / (T * 4);
    const int eb4 = eb0_4 + eb1_4;
    const int nbT = (TN + T - 1) / T;           // thread-per-node over both graphs
    const int nbg = (NN + T - 1) / T;           // per graph

    k_zero<<<512, T>>>();
    k_deg<<<eb4, T>>>(dst0, dst1, E0, E1, eb0_4);
    k_scanA<<<NBLK, SCAN_B>>>();
    k_scanB<<<1, SCAN_B>>>();
    k_scanC<<<NBLK, SCAN_B>>>();
    k_scatter<<<eb4, T>>>(src0, dst0, src1, dst1, E0, E1, eb0_4);
    k_p1csr<<<nbT, T>>>();
    k_p2csr<<<2 * nbg, T>>>(nbg);
    k_coef1<<<2, 32>>>(W_init, b_init, Wg, bg, Wt1, g1, b1);
    k_h1<<<nbT, T>>>();
    k_q1csr<<<nbT, T>>>();
    k_q2F<<<2 * nbg, T>>>(Wt2, nbg);
    k_coef2<<<2, 32>>>(g2, b2);
    k_passG<<<2 * RB, T>>>(RB);
    k_fin<<<1, 32>>>(Wd, bd, Ws0, bs0, Ws1, bs1, Ws2, bs2, Ws3, bs3, Wsim, bsim, (float*)d_out);
}

// round 8
// speedup vs baseline: 1.0516x; 1.0516x over previous
#include <cuda_runtime.h>
#include <cuda_fp16.h>
#include <math.h>

#define NN 500000
#define TN (2 * NN)
#define T 256
#define RB 592   // grid-stride reduction blocks per graph

// ---------------- static device scratch ----------------
// g_zf: deg(2NN) | s1(2NN) | s2(2NN) | nrm(2NN) | ns2(2NN) = 10NN floats
// deg,s1,s2 need zeroing
__device__ __align__(16) float g_zf[10UL * NN];
__device__ __align__(16) __half g_h1s[16UL * NN];  // norm-scaled h1 rows (lane7 = 0)
__device__ __align__(16) __half g_q1[16UL * NN];   // Q1 raw accum (zeroed)
__device__ __align__(16) __half g_q1s[16UL * NN];  // norm^2-scaled Q1
__device__ __align__(16) __half g_q2[16UL * NN];   // Q2 raw accum (zeroed)
__device__ __align__(16) __half g_x2[16UL * NN];
__device__ double g_stats[2][32];
__device__ float  g_coef[2][64];   // [0..7]A [8..15]B [16..23]C [24..31]bn2 scale [32..39]bn2 shift

#define DEGF (g_zf)
#define S1F  (g_zf + 2UL * NN)
#define S2F  (g_zf + 4UL * NN)
#define NRMF (g_zf + 6UL * NN)
#define NS2F (g_zf + 8UL * NN)
#define H1S  ((uint4*)g_h1s)
#define Q1R  ((uint4*)g_q1)
#define Q1S  ((uint4*)g_q1s)
#define Q2R  ((uint4*)g_q2)
#define X2R  ((uint4*)g_x2)

// ---------------- helpers ----------------
template <int K>
__device__ __forceinline__ void block_reduce_add(double* vals, double* out) {
    __shared__ double sm[K][33];
    int lane = threadIdx.x & 31, wid = threadIdx.x >> 5;
#pragma unroll
    for (int k = 0; k < K; k++) {
        double v = vals[k];
#pragma unroll
        for (int o = 16; o; o >>= 1) v += __shfl_down_sync(0xffffffffu, v, o);
        if (lane == 0) sm[k][wid] = v;
    }
    __syncthreads();
    int nw = blockDim.x >> 5;
    if (wid == 0) {
#pragma unroll
        for (int k = 0; k < K; k++) {
            double v = (lane < nw) ? sm[k][lane] : 0.0;
#pragma unroll
            for (int o = 16; o; o >>= 1) v += __shfl_down_sync(0xffffffffu, v, o);
            if (lane == 0) atomicAdd(&out[k], v);
        }
    }
}

__device__ __forceinline__ void red_add_v4h2(__half* addr, uint4 v) {
    asm volatile("red.global.add.noftz.v4.f16x2 [%0], {%1,%2,%3,%4};"
                 :: "l"(addr), "r"(v.x), "r"(v.y), "r"(v.z), "r"(v.w) : "memory");
}
__device__ __forceinline__ unsigned h2u(__half2 v) { return *reinterpret_cast<unsigned*>(&v); }

// ---------------- kernels ----------------
__global__ void k_zero() {
    size_t tid = (size_t)blockIdx.x * blockDim.x + threadIdx.x;
    size_t stride = (size_t)gridDim.x * blockDim.x;
    float4 z = make_float4(0.f, 0.f, 0.f, 0.f);
    for (size_t k = tid; k < 6UL * NN / 4; k += stride) ((float4*)g_zf)[k] = z;   // deg,s1,s2
    for (size_t k = tid; k < 2UL * NN; k += stride) Q1R[k] = make_uint4(0, 0, 0, 0);
    for (size_t k = tid; k < 2UL * NN; k += stride) Q2R[k] = make_uint4(0, 0, 0, 0);
    if (tid < 64) ((double*)g_stats)[tid] = 0.0;
}

__global__ void k_deg(const int* __restrict__ d0, const int* __restrict__ d1,
                      int E0, int E1, int nb0) {
    int b = blockIdx.x, off = 0;
    const int* dst; int E;
    if (b < nb0) { dst = d0; E = E0; }
    else { b -= nb0; dst = d1; E = E1; off = NN; }
    int base = (b * blockDim.x + threadIdx.x) * 4;
    if (base + 3 < E) {
        int4 d = *(const int4*)(dst + base);
        atomicAdd(&DEGF[d.x + off], 1.f); atomicAdd(&DEGF[d.y + off], 1.f);
        atomicAdd(&DEGF[d.z + off], 1.f); atomicAdd(&DEGF[d.w + off], 1.f);
    } else {
        for (int e = base; e < E; e++) atomicAdd(&DEGF[dst[e] + off], 1.f);
    }
}

__global__ void k_norm() {
    int i = blockIdx.x * blockDim.x + threadIdx.x;
    if (i < TN) NRMF[i] = rsqrtf(fmaxf(DEGF[i], 1.0f));
}

__global__ void k_p1(const int* __restrict__ s0, const int* __restrict__ d0,
                     const int* __restrict__ s1, const int* __restrict__ d1,
                     int E0, int E1, int nb0) {
    int b = blockIdx.x, off = 0;
    const int *src, *dst; int E;
    if (b < nb0) { src = s0; dst = d0; E = E0; }
    else { b -= nb0; src = s1; dst = d1; E = E1; off = NN; }
    int base = (b * blockDim.x + threadIdx.x) * 4;
    if (base + 3 < E) {
        int4 s = *(const int4*)(src + base);
        int4 d = *(const int4*)(dst + base);
        float w0 = __ldg(&NRMF[s.x + off]);
        float w1 = __ldg(&NRMF[s.y + off]);
        float w2 = __ldg(&NRMF[s.z + off]);
        float w3 = __ldg(&NRMF[s.w + off]);
        atomicAdd(&S1F[d.x + off], w0);
        atomicAdd(&S1F[d.y + off], w1);
        atomicAdd(&S1F[d.z + off], w2);
        atomicAdd(&S1F[d.w + off], w3);
    } else {
        for (int e = base; e < E; e++)
            atomicAdd(&S1F[dst[e] + off], __ldg(&NRMF[src[e] + off]));
    }
}

__global__ void k_pack() {  // ns2 = norm^2 * s1 (p2's pre-scaled gather source)
    int i = blockIdx.x * blockDim.x + threadIdx.x;
    if (i < TN) {
        float nn = NRMF[i];
        NS2F[i] = nn * nn * S1F[i];
    }
}

__global__ void k_p2(const int* __restrict__ s0, const int* __restrict__ d0,
                     const int* __restrict__ s1, const int* __restrict__ d1,
                     int E0, int E1, int nb0) {
    int b = blockIdx.x, off = 0;
    const int *src, *dst; int E;
    if (b < nb0) { src = s0; dst = d0; E = E0; }
    else { b -= nb0; src = s1; dst = d1; E = E1; off = NN; }
    int base = (b * blockDim.x + threadIdx.x) * 4;
    if (base + 3 < E) {
        int4 s = *(const int4*)(src + base);
        int4 d = *(const int4*)(dst + base);
        float w0 = __ldg(&NS2F[s.x + off]);
        float w1 = __ldg(&NS2F[s.y + off]);
        float w2 = __ldg(&NS2F[s.z + off]);
        float w3 = __ldg(&NS2F[s.w + off]);
        atomicAdd(&S2F[d.x + off], w0);
        atomicAdd(&S2F[d.y + off], w1);
        atomicAdd(&S2F[d.z + off], w2);
        atomicAdd(&S2F[d.w + off], w3);
    } else {
        for (int e = base; e < E; e++)
            atomicAdd(&S2F[dst[e] + off], __ldg(&NS2F[src[e] + off]));
    }
}

__global__ void k_stats1(int nb0) {
    int g = blockIdx.x < nb0 ? 0 : 1;
    int b = g ? blockIdx.x - nb0 : blockIdx.x;
    int off = g * NN;
    double acc[5] = {0, 0, 0, 0, 0};
    int stride = nb0 * blockDim.x;
    for (int i = b * blockDim.x + threadIdx.x; i < NN; i += stride) {
        float nn = NRMF[i + off];
        float p1 = nn * S1F[i + off], p2 = nn * S2F[i + off];
        acc[0] += p1; acc[1] += p2;
        acc[2] += (double)p1 * p1; acc[3] += (double)p2 * p2; acc[4] += (double)p1 * p2;
    }
    block_reduce_add<5>(acc, g_stats[g]);
}

__global__ void k_coef1(const float* __restrict__ W_init, const float* __restrict__ b_init,
                        const float* __restrict__ Wg, const float* __restrict__ bg,
                        const float* __restrict__ Wt1, const float* __restrict__ g1,
                        const float* __restrict__ b1) {
    int g = blockIdx.x;
    if (threadIdx.x != 0) return;
    float xrow[4];
    for (int j = 0; j < 4; j++) {
        float s = b_init[j];
        for (int i = 0; i < 12; i++) s += W_init[i * 4 + j];
        xrow[j] = s;
    }
    float hrow[7];
    for (int k = 0; k < 7; k++) {
        float s = bg[k];
        for (int j = 0; j < 4; j++) s += xrow[j] * Wg[j * 7 + k];
        hrow[k] = 1.0f / (1.0f + expf(-s));
    }
    const double inv_n = 1.0 / (double)NN;
    double m1 = g_stats[g][0] * inv_n, m2 = g_stats[g][1] * inv_n;
    double v1 = g_stats[g][2] * inv_n - m1 * m1;
    double v2 = g_stats[g][3] * inv_n - m2 * m2;
    double c12 = g_stats[g][4] * inv_n - m1 * m2;
    for (int j = 0; j < 7; j++) {
        float a = 0.f, b = 0.f, c = 0.f;
        for (int k = 0; k < 7; k++) {
            a += hrow[k] * Wt1[k * 7 + j];
            b += hrow[k] * Wt1[(7 + k) * 7 + j];
            c += hrow[k] * Wt1[(14 + k) * 7 + j];
        }
        double mean = (double)a + m1 * (double)b + m2 * (double)c;
        double var = (double)b * b * v1 + (double)c * c * v2 + 2.0 * (double)b * c * c12;
        double sc = (double)g1[j] / sqrt(var + 1e-5);
        g_coef[g][j]      = (float)(((double)a - mean) * sc + (double)b1[j]);
        g_coef[g][8 + j]  = (float)((double)b * sc);
        g_coef[g][16 + j] = (float)((double)c * sc);
    }
}

// h1s[i] = norm[i] * relu(A + B p1 + C p2), fp16 row, lane7 = 0
__global__ void k_h1() {
    __shared__ float cf[2][21];
    if (threadIdx.x < 42) {
        int g = threadIdx.x / 21, j = threadIdx.x % 21;
        cf[g][j] = g_coef[g][(j / 7) * 8 + (j % 7)];
    }
    __syncthreads();
    int i = blockIdx.x * blockDim.x + threadIdx.x;
    if (i >= TN) return;
    int g = i >= NN;
    float nn = NRMF[i];
    float p1 = nn * S1F[i], p2 = nn * S2F[i];
    const float* c = cf[g];
    float o[7];
#pragma unroll
    for (int j = 0; j < 7; j++)
        o[j] = nn * fmaxf(c[j] + p1 * c[7 + j] + p2 * c[14 + j], 0.f);
    __half2 h01 = __floats2half2_rn(o[0], o[1]);
    __half2 h23 = __floats2half2_rn(o[2], o[3]);
    __half2 h45 = __floats2half2_rn(o[4], o[5]);
    __half2 h67 = __floats2half2_rn(o[6], 0.f);
    H1S[i] = make_uint4(h2u(h01), h2u(h23), h2u(h45), h2u(h67));
}

// math-free scatter: RED(out[dst] += gather(in[src]))
template <int STEP>   // 1: H1S -> Q1R ; 2: Q1S -> Q2R
__global__ void k_qscat(const int* __restrict__ s0, const int* __restrict__ d0,
                        const int* __restrict__ s1, const int* __restrict__ d1,
                        int E0, int E1, int nb0) {
    int b = blockIdx.x, off = 0;
    const int *src, *dst; int E;
    if (b < nb0) { src = s0; dst = d0; E = E0; }
    else { b -= nb0; src = s1; dst = d1; E = E1; off = NN; }
    const uint4* in = (STEP == 1) ? H1S : Q1S;
    uint4* out = (STEP == 1) ? Q1R : Q2R;
    int base = (b * blockDim.x + threadIdx.x) * 4;
    if (base + 3 < E) {
        int4 s = *(const int4*)(src + base);
        int4 d = *(const int4*)(dst + base);
        uint4 r0 = __ldg(in + s.x + off);
        uint4 r1 = __ldg(in + s.y + off);
        uint4 r2 = __ldg(in + s.z + off);
        uint4 r3 = __ldg(in + s.w + off);
        red_add_v4h2((__half*)(out + d.x + off), r0);
        red_add_v4h2((__half*)(out + d.y + off), r1);
        red_add_v4h2((__half*)(out + d.z + off), r2);
        red_add_v4h2((__half*)(out + d.w + off), r3);
    } else {
        for (int e = base; e < E; e++) {
            uint4 r = __ldg(in + src[e] + off);
            red_add_v4h2((__half*)(out + dst[e] + off), r);
        }
    }
}

// Q1s[i] = norm[i]^2 * Q1[i]  (pre-scale for second propagation)
__global__ void k_scaleQ1() {
    int i = blockIdx.x * blockDim.x + threadIdx.x;
    if (i >= TN) return;
    float nn = NRMF[i];
    __half2 w = __float2half2_rn(nn * nn);
    uint4 r = Q1R[i];
    __half2 p01 = *(__half2*)&r.x, p23 = *(__half2*)&r.y;
    __half2 p45 = *(__half2*)&r.z, p67 = *(__half2*)&r.w;
    Q1S[i] = make_uint4(h2u(__hmul2(p01, w)), h2u(__hmul2(p23, w)),
                        h2u(__hmul2(p45, w)), h2u(__hmul2(p67, w)));
}

__global__ void k_passF(const float* __restrict__ Wt2, int nb0) {
    __shared__ float w[147];
    __shared__ float cf[2][21];
    for (int k = threadIdx.x; k < 147; k += blockDim.x) w[k] = Wt2[k];
    if (threadIdx.x < 42) {
        int gg = threadIdx.x / 21, j = threadIdx.x % 21;
        cf[gg][j] = g_coef[gg][(j / 7) * 8 + (j % 7)];
    }
    __syncthreads();
    int g = blockIdx.x < nb0 ? 0 : 1;
    int b = g ? blockIdx.x - nb0 : blockIdx.x;
    int off = g * NN;
    const float* c = cf[g];
    double acc[14];
#pragma unroll
    for (int k = 0; k < 14; k++) acc[k] = 0.0;
    int stride = nb0 * blockDim.x;
    for (int i = b * blockDim.x + threadIdx.x; i < NN; i += stride) {
        float nn = NRMF[i + off];
        float p1 = nn * S1F[i + off], p2 = nn * S2F[i + off];
        uint4 ar = Q1R[i + off], br = Q2R[i + off];
        float v[21];
#pragma unroll
        for (int j = 0; j < 7; j++)
            v[j] = fmaxf(c[j] + p1 * c[7 + j] + p2 * c[14 + j], 0.f);
        {
            float2 t;
            t = __half22float2(*(__half2*)&ar.x); v[7] = nn * t.x; v[8] = nn * t.y;
            t = __half22float2(*(__half2*)&ar.y); v[9] = nn * t.x; v[10] = nn * t.y;
            t = __half22float2(*(__half2*)&ar.z); v[11] = nn * t.x; v[12] = nn * t.y;
            t = __half22float2(*(__half2*)&ar.w); v[13] = nn * t.x;
            t = __half22float2(*(__half2*)&br.x); v[14] = nn * t.x; v[15] = nn * t.y;
            t = __half22float2(*(__half2*)&br.y); v[16] = nn * t.x; v[17] = nn * t.y;
            t = __half22float2(*(__half2*)&br.z); v[18] = nn * t.x; v[19] = nn * t.y;
            t = __half22float2(*(__half2*)&br.w); v[20] = nn * t.x;
        }
        float xr[7];
#pragma unroll
        for (int j = 0; j < 7; j++) {
            float s = 0.f;
#pragma unroll
            for (int k = 0; k < 21; k++) s += v[k] * w[k * 7 + j];
            xr[j] = s;
        }
        __half2 x01 = __floats2half2_rn(xr[0], xr[1]);
        __half2 x23 = __floats2half2_rn(xr[2], xr[3]);
        __half2 x45 = __floats2half2_rn(xr[4], xr[5]);
        __half2 x67 = __floats2half2_rn(xr[6], 0.f);
        X2R[i + off] = make_uint4(h2u(x01), h2u(x23), h2u(x45), h2u(x67));
#pragma unroll
        for (int j = 0; j < 7; j++) {
            acc[j] += xr[j];
            acc[7 + j] += (double)xr[j] * xr[j];
        }
    }
    block_reduce_add<14>(acc, g_stats[g] + 5);
}

__global__ void k_coef2(const float* __restrict__ g2, const float* __restrict__ b2) {
    int g = blockIdx.x;
    if (threadIdx.x != 0) return;
    const double inv_n = 1.0 / (double)NN;
    for (int j = 0; j < 7; j++) {
        double mean = g_stats[g][5 + j] * inv_n;
        double var = g_stats[g][12 + j] * inv_n - mean * mean;
        double sc = (double)g2[j] / sqrt(var + 1e-5);
        g_coef[g][24 + j] = (float)sc;
        g_coef[g][32 + j] = (float)((double)b2[j] - mean * sc);
    }
}

__global__ void k_passG(int nb0) {
    __shared__ float sc[2][7], sh[2][7];
    if (threadIdx.x < 28) {
        int g = threadIdx.x / 14, j = threadIdx.x % 14;
        if (j < 7) sc[g][j] = g_coef[g][24 + j];
        else sh[g][j - 7] = g_coef[g][32 + j - 7];
    }
    __syncthreads();
    int g = blockIdx.x < nb0 ? 0 : 1;
    int b = g ? blockIdx.x - nb0 : blockIdx.x;
    int off = g * NN;
    double acc[7] = {0, 0, 0, 0, 0, 0, 0};
    int stride = nb0 * blockDim.x;
    for (int i = b * blockDim.x + threadIdx.x; i < NN; i += stride) {
        uint4 xr = X2R[i + off];
        float v[7];
        float2 t;
        t = __half22float2(*(__half2*)&xr.x); v[0] = t.x; v[1] = t.y;
        t = __half22float2(*(__half2*)&xr.y); v[2] = t.x; v[3] = t.y;
        t = __half22float2(*(__half2*)&xr.z); v[4] = t.x; v[5] = t.y;
        t = __half22float2(*(__half2*)&xr.w); v[6] = t.x;
#pragma unroll
        for (int j = 0; j < 7; j++)
            acc[j] += fmaxf(v[j] * sc[g][j] + sh[g][j], 0.f);
    }
    block_reduce_add<7>(acc, g_stats[g] + 19);
}

__global__ void k_fin(const float* __restrict__ Wd, const float* __restrict__ bd,
                      const float* __restrict__ Ws0, const float* __restrict__ bs0,
                      const float* __restrict__ Ws1, const float* __restrict__ bs1,
                      const float* __restrict__ Ws2, const float* __restrict__ bs2,
                      const float* __restrict__ Ws3, const float* __restrict__ bs3,
                      const float* __restrict__ Wsim, const float* __restrict__ bsim,
                      float* __restrict__ out) {
    if (threadIdx.x != 0) return;
    const double inv_n = 1.0 / (double)NN;
    float h[22];
    for (int g = 0; g < 2; g++)
        for (int m = 0; m < 11; m++) {
            double s = (double)bd[m];
            for (int j = 0; j < 7; j++)
                s += (g_stats[g][19 + j] * inv_n) * (double)Wd[j * 11 + m];
            h[g * 11 + m] = (float)s;
        }
    float t[7], u[7];
    for (int j = 0; j < 7; j++) {
        float s = bs0[j];
        for (int k = 0; k < 22; k++) s += h[k] * Ws0[k * 7 + j];
        t[j] = s;
    }
    for (int j = 0; j < 7; j++) {
        float s = bs1[j];
        for (int k = 0; k < 7; k++) s += t[k] * Ws1[k * 7 + j];
        u[j] = fmaxf(s, 0.f);
    }
    for (int j = 0; j < 7; j++) {
        float s = bs2[j];
        for (int k = 0; k < 7; k++) s += u[k] * Ws2[k * 7 + j];
        t[j] = fmaxf(s, 0.f);
    }
    for (int j = 0; j < 7; j++) {
        float s = bs3[j];
        for (int k = 0; k < 7; k++) s += t[k] * Ws3[k * 7 + j];
        u[j] = fmaxf(s, 0.f);
    }
    for (int m = 0; m < 12; m++) {
        float s = bsim[m];
        for (int j = 0; j < 7; j++) s += u[j] * Wsim[j * 12 + m];
        out[m] = 1.0f / (1.0f + expf(-s));
    }
}

// ---------------- launch ----------------
extern "C" void kernel_launch(void* const* d_in, const int* in_sizes, int n_in,
                              void* d_out, int out_size) {
    const int* src0 = (const int*)d_in[0];
    const int* dst0 = (const int*)d_in[1];
    const int* src1 = (const int*)d_in[2];
    const int* dst1 = (const int*)d_in[3];
    const float* W_init = (const float*)d_in[5];
    const float* b_init = (const float*)d_in[6];
    const float* Wg  = (const float*)d_in[7];
    const float* bg  = (const float*)d_in[8];
    const float* Wt1 = (const float*)d_in[9];
    const float* g1  = (const float*)d_in[10];
    const float* b1  = (const float*)d_in[11];
    const float* Wt2 = (const float*)d_in[12];
    const float* g2  = (const float*)d_in[13];
    const float* b2  = (const float*)d_in[14];
    const float* Wd  = (const float*)d_in[15];
    const float* bd  = (const float*)d_in[16];
    const float* Ws0 = (const float*)d_in[17];
    const float* bs0 = (const float*)d_in[18];
    const float* Ws1 = (const float*)d_in[19];
    const float* bs1 = (const float*)d_in[20];
    const float* Ws2 = (const float*)d_in[21];
    const float* bs2 = (const float*)d_in[22];
    const float* Ws3 = (const float*)d_in[23];
    const float* bs3 = (const float*)d_in[24];
    const float* Wsim = (const float*)d_in[25];
    const float* bsim = (const float*)d_in[26];

    const int E0 = in_sizes[0];
    const int E1 = in_sizes[2];
    const int eb0_4 = (E0 + T * 4 - 1) / (T * 4);
    const int eb1_4 = (E1 + T * 4 - 1) / (T * 4);
    const int eb4 = eb0_4 + eb1_4;
    const int nbT = (TN + T - 1) / T;

    k_zero<<<2368, T>>>();
    k_deg<<<eb4, T>>>(dst0, dst1, E0, E1, eb0_4);
    k_norm<<<nbT, T>>>();
    k_p1<<<eb4, T>>>(src0, dst0, src1, dst1, E0, E1, eb0_4);
    k_pack<<<nbT, T>>>();
    k_p2<<<eb4, T>>>(src0, dst0, src1, dst1, E0, E1, eb0_4);
    k_stats1<<<2 * RB, T>>>(RB);
    k_coef1<<<2, 32>>>(W_init, b_init, Wg, bg, Wt1, g1, b1);
    k_h1<<<nbT, T>>>();
    k_qscat<1><<<eb4, T>>>(src0, dst0, src1, dst1, E0, E1, eb0_4);
    k_scaleQ1<<<nbT, T>>>();
    k_qscat<2><<<eb4, T>>>(src0, dst0, src1, dst1, E0, E1, eb0_4);
    k_passF<<<2 * RB, T>>>(Wt2, RB);
    k_coef2<<<2, 32>>>(g2, b2);
    k_passG<<<2 * RB, T>>>(RB);
    k_fin<<<1, 32>>>(Wd, bd, Ws0, bs0, Ws1, bs1, Ws2, bs2, Ws3, bs3, Wsim, bsim, (float*)d_out);
}

// round 9
// speedup vs baseline: 1.0938x; 1.0402x over previous
#include <cuda_runtime.h>
#include <cuda_fp16.h>
#include <math.h>

#define NN 500000
#define TN (2 * NN)
#define T 256
#define RB 592   // grid-stride reduction blocks per graph

// ---------------- static device scratch ----------------
// g_zf: deg(2NN) | s1(2NN) | s2(2NN) | nrm(2NN) | ns2(2NN) = 10NN floats
__device__ __align__(16) float g_zf[10UL * NN];
__device__ __align__(16) __half g_h1s[16UL * NN];  // norm-scaled h1 rows (lane7 = 0)
__device__ __align__(16) __half g_q1[16UL * NN];   // Q1 raw accum (zeroed)
__device__ __align__(16) __half g_q1s[16UL * NN];  // norm^2-scaled Q1
__device__ __align__(16) __half g_q2[16UL * NN];   // Q2 raw accum (zeroed)
__device__ __align__(16) __half g_x2[16UL * NN];
__device__ double g_stats[2][32];
__device__ float  g_coef[2][64];

#define DEGF (g_zf)
#define S1F  (g_zf + 2UL * NN)
#define S2F  (g_zf + 4UL * NN)
#define NRMF (g_zf + 6UL * NN)
#define NS2F (g_zf + 8UL * NN)
#define H1S  ((uint4*)g_h1s)
#define Q1R  ((uint4*)g_q1)
#define Q1S  ((uint4*)g_q1s)
#define Q2R  ((uint4*)g_q2)
#define X2R  ((uint4*)g_x2)

// ---------------- helpers ----------------
template <int K>
__device__ __forceinline__ void block_reduce_add(double* vals, double* out) {
    __shared__ double sm[K][33];
    int lane = threadIdx.x & 31, wid = threadIdx.x >> 5;
#pragma unroll
    for (int k = 0; k < K; k++) {
        double v = vals[k];
#pragma unroll
        for (int o = 16; o; o >>= 1) v += __shfl_down_sync(0xffffffffu, v, o);
        if (lane == 0) sm[k][wid] = v;
    }
    __syncthreads();
    int nw = blockDim.x >> 5;
    if (wid == 0) {
#pragma unroll
        for (int k = 0; k < K; k++) {
            double v = (lane < nw) ? sm[k][lane] : 0.0;
#pragma unroll
            for (int o = 16; o; o >>= 1) v += __shfl_down_sync(0xffffffffu, v, o);
            if (lane == 0) atomicAdd(&out[k], v);
        }
    }
}

__device__ __forceinline__ void red_add_v4h2(__half* addr, uint4 v) {
    asm volatile("red.global.add.noftz.v4.f16x2 [%0], {%1,%2,%3,%4};"
                 :: "l"(addr), "r"(v.x), "r"(v.y), "r"(v.z), "r"(v.w) : "memory");
}
__device__ __forceinline__ unsigned h2u(__half2 v) { return *reinterpret_cast<unsigned*>(&v); }

// ---------------- kernels (per-graph: off = g*NN) ----------------
__global__ void k_zero() {
    size_t tid = (size_t)blockIdx.x * blockDim.x + threadIdx.x;
    size_t stride = (size_t)gridDim.x * blockDim.x;
    float4 z = make_float4(0.f, 0.f, 0.f, 0.f);
    for (size_t k = tid; k < 6UL * NN / 4; k += stride) ((float4*)g_zf)[k] = z;
    for (size_t k = tid; k < 2UL * NN; k += stride) Q1R[k] = make_uint4(0, 0, 0, 0);
    for (size_t k = tid; k < 2UL * NN; k += stride) Q2R[k] = make_uint4(0, 0, 0, 0);
    if (tid < 64) ((double*)g_stats)[tid] = 0.0;
}

__global__ void k_deg(const int* __restrict__ dst, int E, int off) {
    int base = (blockIdx.x * blockDim.x + threadIdx.x) * 4;
    if (base + 3 < E) {
        int4 d = *(const int4*)(dst + base);
        atomicAdd(&DEGF[d.x + off], 1.f); atomicAdd(&DEGF[d.y + off], 1.f);
        atomicAdd(&DEGF[d.z + off], 1.f); atomicAdd(&DEGF[d.w + off], 1.f);
    } else {
        for (int e = base; e < E; e++) atomicAdd(&DEGF[dst[e] + off], 1.f);
    }
}

__global__ void k_norm(int off) {
    int i = blockIdx.x * blockDim.x + threadIdx.x;
    if (i < NN) NRMF[i + off] = rsqrtf(fmaxf(DEGF[i + off], 1.0f));
}

__global__ void k_p1(const int* __restrict__ src, const int* __restrict__ dst, int E, int off) {
    int base = (blockIdx.x * blockDim.x + threadIdx.x) * 4;
    if (base + 3 < E) {
        int4 s = *(const int4*)(src + base);
        int4 d = *(const int4*)(dst + base);
        float w0 = __ldg(&NRMF[s.x + off]);
        float w1 = __ldg(&NRMF[s.y + off]);
        float w2 = __ldg(&NRMF[s.z + off]);
        float w3 = __ldg(&NRMF[s.w + off]);
        atomicAdd(&S1F[d.x + off], w0);
        atomicAdd(&S1F[d.y + off], w1);
        atomicAdd(&S1F[d.z + off], w2);
        atomicAdd(&S1F[d.w + off], w3);
    } else {
        for (int e = base; e < E; e++)
            atomicAdd(&S1F[dst[e] + off], __ldg(&NRMF[src[e] + off]));
    }
}

__global__ void k_pack(int off) {  // ns2 = norm^2 * s1
    int i = blockIdx.x * blockDim.x + threadIdx.x;
    if (i < NN) {
        float nn = NRMF[i + off];
        NS2F[i + off] = nn * nn * S1F[i + off];
    }
}

__global__ void k_p2(const int* __restrict__ src, const int* __restrict__ dst, int E, int off) {
    int base = (blockIdx.x * blockDim.x + threadIdx.x) * 4;
    if (base + 3 < E) {
        int4 s = *(const int4*)(src + base);
        int4 d = *(const int4*)(dst + base);
        float w0 = __ldg(&NS2F[s.x + off]);
        float w1 = __ldg(&NS2F[s.y + off]);
        float w2 = __ldg(&NS2F[s.z + off]);
        float w3 = __ldg(&NS2F[s.w + off]);
        atomicAdd(&S2F[d.x + off], w0);
        atomicAdd(&S2F[d.y + off], w1);
        atomicAdd(&S2F[d.z + off], w2);
        atomicAdd(&S2F[d.w + off], w3);
    } else {
        for (int e = base; e < E; e++)
            atomicAdd(&S2F[dst[e] + off], __ldg(&NS2F[src[e] + off]));
    }
}

__global__ void k_stats1(int g) {
    int off = g * NN;
    double acc[5] = {0, 0, 0, 0, 0};
    for (int i = blockIdx.x * blockDim.x + threadIdx.x; i < NN; i += RB * T) {
        float nn = NRMF[i + off];
        float p1 = nn * S1F[i + off], p2 = nn * S2F[i + off];
        acc[0] += p1; acc[1] += p2;
        acc[2] += (double)p1 * p1; acc[3] += (double)p2 * p2; acc[4] += (double)p1 * p2;
    }
    block_reduce_add<5>(acc, g_stats[g]);
}

__global__ void k_coef1(int g, const float* __restrict__ W_init, const float* __restrict__ b_init,
                        const float* __restrict__ Wg, const float* __restrict__ bg,
                        const float* __restrict__ Wt1, const float* __restrict__ g1,
                        const float* __restrict__ b1) {
    if (threadIdx.x != 0) return;
    float xrow[4];
    for (int j = 0; j < 4; j++) {
        float s = b_init[j];
        for (int i = 0; i < 12; i++) s += W_init[i * 4 + j];
        xrow[j] = s;
    }
    float hrow[7];
    for (int k = 0; k < 7; k++) {
        float s = bg[k];
        for (int j = 0; j < 4; j++) s += xrow[j] * Wg[j * 7 + k];
        hrow[k] = 1.0f / (1.0f + expf(-s));
    }
    const double inv_n = 1.0 / (double)NN;
    double m1 = g_stats[g][0] * inv_n, m2 = g_stats[g][1] * inv_n;
    double v1 = g_stats[g][2] * inv_n - m1 * m1;
    double v2 = g_stats[g][3] * inv_n - m2 * m2;
    double c12 = g_stats[g][4] * inv_n - m1 * m2;
    for (int j = 0; j < 7; j++) {
        float a = 0.f, b = 0.f, c = 0.f;
        for (int k = 0; k < 7; k++) {
            a += hrow[k] * Wt1[k * 7 + j];
            b += hrow[k] * Wt1[(7 + k) * 7 + j];
            c += hrow[k] * Wt1[(14 + k) * 7 + j];
        }
        double mean = (double)a + m1 * (double)b + m2 * (double)c;
        double var = (double)b * b * v1 + (double)c * c * v2 + 2.0 * (double)b * c * c12;
        double sc = (double)g1[j] / sqrt(var + 1e-5);
        g_coef[g][j]      = (float)(((double)a - mean) * sc + (double)b1[j]);
        g_coef[g][8 + j]  = (float)((double)b * sc);
        g_coef[g][16 + j] = (float)((double)c * sc);
    }
}

// h1s[i] = norm[i] * relu(A + B p1 + C p2)
__global__ void k_h1(int g) {
    __shared__ float cf[21];
    if (threadIdx.x < 21)
        cf[threadIdx.x] = g_coef[g][(threadIdx.x / 7) * 8 + threadIdx.x % 7];
    __syncthreads();
    int i = blockIdx.x * blockDim.x + threadIdx.x;
    if (i >= NN) return;
    i += g * NN;
    float nn = NRMF[i];
    float p1 = nn * S1F[i], p2 = nn * S2F[i];
    float o[7];
#pragma unroll
    for (int j = 0; j < 7; j++)
        o[j] = nn * fmaxf(cf[j] + p1 * cf[7 + j] + p2 * cf[14 + j], 0.f);
    __half2 h01 = __floats2half2_rn(o[0], o[1]);
    __half2 h23 = __floats2half2_rn(o[2], o[3]);
    __half2 h45 = __floats2half2_rn(o[4], o[5]);
    __half2 h67 = __floats2half2_rn(o[6], 0.f);
    H1S[i] = make_uint4(h2u(h01), h2u(h23), h2u(h45), h2u(h67));
}

// math-free scatter: RED(out[dst] += gather(in[src]))
template <int STEP>   // 1: H1S -> Q1R ; 2: Q1S -> Q2R
__global__ void k_qscat(const int* __restrict__ src, const int* __restrict__ dst, int E, int off) {
    const uint4* in = (STEP == 1) ? H1S : Q1S;
    uint4* out = (STEP == 1) ? Q1R : Q2R;
    int base = (blockIdx.x * blockDim.x + threadIdx.x) * 4;
    if (base + 3 < E) {
        int4 s = *(const int4*)(src + base);
        int4 d = *(const int4*)(dst + base);
        uint4 r0 = __ldg(in + s.x + off);
        uint4 r1 = __ldg(in + s.y + off);
        uint4 r2 = __ldg(in + s.z + off);
        uint4 r3 = __ldg(in + s.w + off);
        red_add_v4h2((__half*)(out + d.x + off), r0);
        red_add_v4h2((__half*)(out + d.y + off), r1);
        red_add_v4h2((__half*)(out + d.z + off), r2);
        red_add_v4h2((__half*)(out + d.w + off), r3);
    } else {
        for (int e = base; e < E; e++) {
            uint4 r = __ldg(in + src[e] + off);
            red_add_v4h2((__half*)(out + dst[e] + off), r);
        }
    }
}

__global__ void k_scaleQ1(int off) {
    int i = blockIdx.x * blockDim.x + threadIdx.x;
    if (i >= NN) return;
    i += off;
    float nn = NRMF[i];
    __half2 w = __float2half2_rn(nn * nn);
    uint4 r = Q1R[i];
    __half2 p01 = *(__half2*)&r.x, p23 = *(__half2*)&r.y;
    __half2 p45 = *(__half2*)&r.z, p67 = *(__half2*)&r.w;
    Q1S[i] = make_uint4(h2u(__hmul2(p01, w)), h2u(__hmul2(p23, w)),
                        h2u(__hmul2(p45, w)), h2u(__hmul2(p67, w)));
}

__global__ void k_passF(int g, const float* __restrict__ Wt2) {
    __shared__ float w[147];
    __shared__ float cf[21];
    for (int k = threadIdx.x; k < 147; k += blockDim.x) w[k] = Wt2[k];
    if (threadIdx.x < 21)
        cf[threadIdx.x] = g_coef[g][(threadIdx.x / 7) * 8 + threadIdx.x % 7];
    __syncthreads();
    int off = g * NN;
    double acc[14];
#pragma unroll
    for (int k = 0; k < 14; k++) acc[k] = 0.0;
    for (int i = blockIdx.x * blockDim.x + threadIdx.x; i < NN; i += RB * T) {
        float nn = NRMF[i + off];
        float p1 = nn * S1F[i + off], p2 = nn * S2F[i + off];
        uint4 ar = Q1R[i + off], br = Q2R[i + off];
        float v[21];
#pragma unroll
        for (int j = 0; j < 7; j++)
            v[j] = fmaxf(cf[j] + p1 * cf[7 + j] + p2 * cf[14 + j], 0.f);
        {
            float2 t;
            t = __half22float2(*(__half2*)&ar.x); v[7] = nn * t.x; v[8] = nn * t.y;
            t = __half22float2(*(__half2*)&ar.y); v[9] = nn * t.x; v[10] = nn * t.y;
            t = __half22float2(*(__half2*)&ar.z); v[11] = nn * t.x; v[12] = nn * t.y;
            t = __half22float2(*(__half2*)&ar.w); v[13] = nn * t.x;
            t = __half22float2(*(__half2*)&br.x); v[14] = nn * t.x; v[15] = nn * t.y;
            t = __half22float2(*(__half2*)&br.y); v[16] = nn * t.x; v[17] = nn * t.y;
            t = __half22float2(*(__half2*)&br.z); v[18] = nn * t.x; v[19] = nn * t.y;
            t = __half22float2(*(__half2*)&br.w); v[20] = nn * t.x;
        }
        float xr[7];
#pragma unroll
        for (int j = 0; j < 7; j++) {
            float s = 0.f;
#pragma unroll
            for (int k = 0; k < 21; k++) s += v[k] * w[k * 7 + j];
            xr[j] = s;
        }
        __half2 x01 = __floats2half2_rn(xr[0], xr[1]);
        __half2 x23 = __floats2half2_rn(xr[2], xr[3]);
        __half2 x45 = __floats2half2_rn(xr[4], xr[5]);
        __half2 x67 = __floats2half2_rn(xr[6], 0.f);
        X2R[i + off] = make_uint4(h2u(x01), h2u(x23), h2u(x45), h2u(x67));
#pragma unroll
        for (int j = 0; j < 7; j++) {
            acc[j] += xr[j];
            acc[7 + j] += (double)xr[j] * xr[j];
        }
    }
    block_reduce_add<14>(acc, g_stats[g] + 5);
}

__global__ void k_coef2(int g, const float* __restrict__ g2, const float* __restrict__ b2) {
    if (threadIdx.x != 0) return;
    const double inv_n = 1.0 / (double)NN;
    for (int j = 0; j < 7; j++) {
        double mean = g_stats[g][5 + j] * inv_n;
        double var = g_stats[g][12 + j] * inv_n - mean * mean;
        double sc = (double)g2[j] / sqrt(var + 1e-5);
        g_coef[g][24 + j] = (float)sc;
        g_coef[g][32 + j] = (float)((double)b2[j] - mean * sc);
    }
}

__global__ void k_passG(int g) {
    __shared__ float sc[7], sh[7];
    if (threadIdx.x < 14) {
        int j = threadIdx.x;
        if (j < 7) sc[j] = g_coef[g][24 + j];
        else sh[j - 7] = g_coef[g][32 + j - 7];
    }
    __syncthreads();
    int off = g * NN;
    double acc[7] = {0, 0, 0, 0, 0, 0, 0};
    for (int i = blockIdx.x * blockDim.x + threadIdx.x; i < NN; i += RB * T) {
        uint4 xr = X2R[i + off];
        float v[7];
        float2 t;
        t = __half22float2(*(__half2*)&xr.x); v[0] = t.x; v[1] = t.y;
        t = __half22float2(*(__half2*)&xr.y); v[2] = t.x; v[3] = t.y;
        t = __half22float2(*(__half2*)&xr.z); v[4] = t.x; v[5] = t.y;
        t = __half22float2(*(__half2*)&xr.w); v[6] = t.x;
#pragma unroll
        for (int j = 0; j < 7; j++)
            acc[j] += fmaxf(v[j] * sc[j] + sh[j], 0.f);
    }
    block_reduce_add<7>(acc, g_stats[g] + 19);
}

__global__ void k_fin(const float* __restrict__ Wd, const float* __restrict__ bd,
                      const float* __restrict__ Ws0, const float* __restrict__ bs0,
                      const float* __restrict__ Ws1, const float* __restrict__ bs1,
                      const float* __restrict__ Ws2, const float* __restrict__ bs2,
                      const float* __restrict__ Ws3, const float* __restrict__ bs3,
                      const float* __restrict__ Wsim, const float* __restrict__ bsim,
                      float* __restrict__ out) {
    if (threadIdx.x != 0) return;
    const double inv_n = 1.0 / (double)NN;
    float h[22];
    for (int g = 0; g < 2; g++)
        for (int m = 0; m < 11; m++) {
            double s = (double)bd[m];
            for (int j = 0; j < 7; j++)
                s += (g_stats[g][19 + j] * inv_n) * (double)Wd[j * 11 + m];
            h[g * 11 + m] = (float)s;
        }
    float t[7], u[7];
    for (int j = 0; j < 7; j++) {
        float s = bs0[j];
        for (int k = 0; k < 22; k++) s += h[k] * Ws0[k * 7 + j];
        t[j] = s;
    }
    for (int j = 0; j < 7; j++) {
        float s = bs1[j];
        for (int k = 0; k < 7; k++) s += t[k] * Ws1[k * 7 + j];
        u[j] = fmaxf(s, 0.f);
    }
    for (int j = 0; j < 7; j++) {
        float s = bs2[j];
        for (int k = 0; k < 7; k++) s += u[k] * Ws2[k * 7 + j];
        t[j] = fmaxf(s, 0.f);
    }
    for (int j = 0; j < 7; j++) {
        float s = bs3[j];
        for (int k = 0; k < 7; k++) s += t[k] * Ws3[k * 7 + j];
        u[j] = fmaxf(s, 0.f);
    }
    for (int m = 0; m < 12; m++) {
        float s = bsim[m];
        for (int j = 0; j < 7; j++) s += u[j] * Wsim[j * 12 + m];
        out[m] = 1.0f / (1.0f + expf(-s));
    }
}

// ---------------- launch ----------------
extern "C" void kernel_launch(void* const* d_in, const int* in_sizes, int n_in,
                              void* d_out, int out_size) {
    const int* src0 = (const int*)d_in[0];
    const int* dst0 = (const int*)d_in[1];
    const int* src1 = (const int*)d_in[2];
    const int* dst1 = (const int*)d_in[3];
    const float* W_init = (const float*)d_in[5];
    const float* b_init = (const float*)d_in[6];
    const float* Wg  = (const float*)d_in[7];
    const float* bg  = (const float*)d_in[8];
    const float* Wt1 = (const float*)d_in[9];
    const float* g1  = (const float*)d_in[10];
    const float* b1  = (const float*)d_in[11];
    const float* Wt2 = (const float*)d_in[12];
    const float* g2  = (const float*)d_in[13];
    const float* b2  = (const float*)d_in[14];
    const float* Wd  = (const float*)d_in[15];
    const float* bd  = (const float*)d_in[16];
    const float* Ws0 = (const float*)d_in[17];
    const float* bs0 = (const float*)d_in[18];
    const float* Ws1 = (const float*)d_in[19];
    const float* bs1 = (const float*)d_in[20];
    const float* Ws2 = (const float*)d_in[21];
    const float* bs2 = (const float*)d_in[22];
    const float* Ws3 = (const float*)d_in[23];
    const float* bs3 = (const float*)d_in[24];
    const float* Wsim = (const float*)d_in[25];
    const float* bsim = (const float*)d_in[26];

    // one-time stream/event setup (host objects; no device allocations)
    static cudaStream_t s1 = 0;
    static cudaEvent_t ev_fork = 0, ev_stag = 0, ev_join = 0;
    static int inited = 0;
    if (!inited) {
        if (cudaStreamCreateWithFlags(&s1, cudaStreamNonBlocking) != cudaSuccess) s1 = 0;
        cudaEventCreateWithFlags(&ev_fork, cudaEventDisableTiming);
        cudaEventCreateWithFlags(&ev_stag, cudaEventDisableTiming);
        cudaEventCreateWithFlags(&ev_join, cudaEventDisableTiming);
        inited = 1;
    }

    const int E0 = in_sizes[0];
    const int E1 = in_sizes[2];
    const int eb0 = (E0 + T * 4 - 1) / (T * 4);
    const int eb1 = (E1 + T * 4 - 1) / (T * 4);
    const int nbg = (NN + T - 1) / T;

    // shared zero, then fork
    k_zero<<<2368, T>>>();
    cudaEventRecord(ev_fork, 0);

    // ---- graph 0 on default stream ----
    k_deg<<<eb0, T>>>(dst0, E0, 0);
    cudaEventRecord(ev_stag, 0);   // graph 1 starts its edge work after deg0
    k_norm<<<nbg, T>>>(0);
    k_p1<<<eb0, T>>>(src0, dst0, E0, 0);
    k_pack<<<nbg, T>>>(0);
    k_p2<<<eb0, T>>>(src0, dst0, E0, 0);
    k_stats1<<<RB, T>>>(0);
    k_coef1<<<1, 32>>>(0, W_init, b_init, Wg, bg, Wt1, g1, b1);
    k_h1<<<nbg, T>>>(0);
    k_qscat<1><<<eb0, T>>>(src0, dst0, E0, 0);
    k_scaleQ1<<<nbg, T>>>(0);
    k_qscat<2><<<eb0, T>>>(src0, dst0, E0, 0);
    k_passF<<<RB, T>>>(0, Wt2);
    k_coef2<<<1, 32>>>(0, g2, b2);
    k_passG<<<RB, T>>>(0);

    // ---- graph 1 on second stream (staggered by one edge pass) ----
    cudaStreamWaitEvent(s1, ev_fork, 0);
    cudaStreamWaitEvent(s1, ev_stag, 0);
    k_deg<<<eb1, T, 0, s1>>>(dst1, E1, NN);
    k_norm<<<nbg, T, 0, s1>>>(NN);
    k_p1<<<eb1, T, 0, s1>>>(src1, dst1, E1, NN);
    k_pack<<<nbg, T, 0, s1>>>(NN);
    k_p2<<<eb1, T, 0, s1>>>(src1, dst1, E1, NN);
    k_stats1<<<RB, T, 0, s1>>>(1);
    k_coef1<<<1, 32, 0, s1>>>(1, W_init, b_init, Wg, bg, Wt1, g1, b1);
    k_h1<<<nbg, T, 0, s1>>>(1);
    k_qscat<1><<<eb1, T, 0, s1>>>(src1, dst1, E1, NN);
    k_scaleQ1<<<nbg, T, 0, s1>>>(NN);
    k_qscat<2><<<eb1, T, 0, s1>>>(src1, dst1, E1, NN);
    k_passF<<<RB, T, 0, s1>>>(1, Wt2);
    k_coef2<<<1, 32, 0, s1>>>(1, g2, b2);
    k_passG<<<RB, T, 0, s1>>>(1);
    cudaEventRecord(ev_join, s1);

    // ---- join + head ----
    cudaStreamWaitEvent(0, ev_join, 0);
    k_fin<<<1, 32>>>(Wd, bd, Ws0, bs0, Ws1, bs1, Ws2, bs2, Ws3, bs3, Wsim, bsim, (float*)d_out);
}

// round 10
// speedup vs baseline: 1.1159x; 1.0202x over previous
#include <cuda_runtime.h>
#include <cuda_fp16.h>
#include <math.h>

#define NN 500000
#define TN (2 * NN)
#define T 256
#define RB 592   // grid-stride reduction blocks per graph

// ---------------- static device scratch ----------------
// g_zf: deg(2NN) | s1(2NN) | s2(2NN) | nrm(2NN) | ns2(2NN) = 10NN floats
__device__ __align__(16) float g_zf[10UL * NN];
__device__ __align__(16) __half g_h1s[16UL * NN];  // norm-scaled h1 rows (lane7 = 0)
__device__ __align__(16) __half g_q1[16UL * NN];   // Q1 accum; lane7 = norm^2 (prop-2 weight)
__device__ __align__(16) __half g_q2[16UL * NN];   // Q2 accum (zeroed by k_h1)
__device__ __align__(16) __half g_x2[16UL * NN];
__device__ double g_stats[2][32];
__device__ float  g_coef[2][64];

#define DEGF (g_zf)
#define S1F  (g_zf + 2UL * NN)
#define S2F  (g_zf + 4UL * NN)
#define NRMF (g_zf + 6UL * NN)
#define NS2F (g_zf + 8UL * NN)
#define H1S  ((uint4*)g_h1s)
#define Q1R  ((uint4*)g_q1)
#define Q2R  ((uint4*)g_q2)
#define X2R  ((uint4*)g_x2)

// ---------------- helpers ----------------
template <int K>
__device__ __forceinline__ void block_reduce_add(double* vals, double* out) {
    __shared__ double sm[K][33];
    int lane = threadIdx.x & 31, wid = threadIdx.x >> 5;
#pragma unroll
    for (int k = 0; k < K; k++) {
        double v = vals[k];
#pragma unroll
        for (int o = 16; o; o >>= 1) v += __shfl_down_sync(0xffffffffu, v, o);
        if (lane == 0) sm[k][wid] = v;
    }
    __syncthreads();
    int nw = blockDim.x >> 5;
    if (wid == 0) {
#pragma unroll
        for (int k = 0; k < K; k++) {
            double v = (lane < nw) ? sm[k][lane] : 0.0;
#pragma unroll
            for (int o = 16; o; o >>= 1) v += __shfl_down_sync(0xffffffffu, v, o);
            if (lane == 0) atomicAdd(&out[k], v);
        }
    }
}

__device__ __forceinline__ void red_add_v4h2(__half* addr, uint4 v) {
    asm volatile("red.global.add.noftz.v4.f16x2 [%0], {%1,%2,%3,%4};"
                 :: "l"(addr), "r"(v.x), "r"(v.y), "r"(v.z), "r"(v.w) : "memory");
}
__device__ __forceinline__ unsigned h2u(__half2 v) { return *reinterpret_cast<unsigned*>(&v); }

// ---------------- kernels (per-graph: off = g*NN) ----------------
__global__ void k_zero() {
    size_t tid = (size_t)blockIdx.x * blockDim.x + threadIdx.x;
    size_t stride = (size_t)gridDim.x * blockDim.x;
    float4 z = make_float4(0.f, 0.f, 0.f, 0.f);
    for (size_t k = tid; k < 6UL * NN / 4; k += stride) ((float4*)g_zf)[k] = z;  // deg,s1,s2
    if (tid < 64) ((double*)g_stats)[tid] = 0.0;
}

__global__ void k_deg(const int* __restrict__ dst, int E, int off) {
    int base = (blockIdx.x * blockDim.x + threadIdx.x) * 4;
    if (base + 3 < E) {
        int4 d = *(const int4*)(dst + base);
        atomicAdd(&DEGF[d.x + off], 1.f); atomicAdd(&DEGF[d.y + off], 1.f);
        atomicAdd(&DEGF[d.z + off], 1.f); atomicAdd(&DEGF[d.w + off], 1.f);
    } else {
        for (int e = base; e < E; e++) atomicAdd(&DEGF[dst[e] + off], 1.f);
    }
}

__global__ void k_norm(int off) {
    int i = blockIdx.x * blockDim.x + threadIdx.x;
    if (i < NN) NRMF[i + off] = rsqrtf(fmaxf(DEGF[i + off], 1.0f));
}

__global__ void k_p1(const int* __restrict__ src, const int* __restrict__ dst, int E, int off) {
    int base = (blockIdx.x * blockDim.x + threadIdx.x) * 4;
    if (base + 3 < E) {
        int4 s = *(const int4*)(src + base);
        int4 d = *(const int4*)(dst + base);
        float w0 = __ldg(&NRMF[s.x + off]);
        float w1 = __ldg(&NRMF[s.y + off]);
        float w2 = __ldg(&NRMF[s.z + off]);
        float w3 = __ldg(&NRMF[s.w + off]);
        atomicAdd(&S1F[d.x + off], w0);
        atomicAdd(&S1F[d.y + off], w1);
        atomicAdd(&S1F[d.z + off], w2);
        atomicAdd(&S1F[d.w + off], w3);
    } else {
        for (int e = base; e < E; e++)
            atomicAdd(&S1F[dst[e] + off], __ldg(&NRMF[src[e] + off]));
    }
}

__global__ void k_pack(int off) {  // ns2 = norm^2 * s1
    int i = blockIdx.x * blockDim.x + threadIdx.x;
    if (i < NN) {
        float nn = NRMF[i + off];
        NS2F[i + off] = nn * nn * S1F[i + off];
    }
}

__global__ void k_p2(const int* __restrict__ src, const int* __restrict__ dst, int E, int off) {
    int base = (blockIdx.x * blockDim.x + threadIdx.x) * 4;
    if (base + 3 < E) {
        int4 s = *(const int4*)(src + base);
        int4 d = *(const int4*)(dst + base);
        float w0 = __ldg(&NS2F[s.x + off]);
        float w1 = __ldg(&NS2F[s.y + off]);
        float w2 = __ldg(&NS2F[s.z + off]);
        float w3 = __ldg(&NS2F[s.w + off]);
        atomicAdd(&S2F[d.x + off], w0);
        atomicAdd(&S2F[d.y + off], w1);
        atomicAdd(&S2F[d.z + off], w2);
        atomicAdd(&S2F[d.w + off], w3);
    } else {
        for (int e = base; e < E; e++)
            atomicAdd(&S2F[dst[e] + off], __ldg(&NS2F[src[e] + off]));
    }
}

__global__ void k_stats1(int g) {
    int off = g * NN;
    double acc[5] = {0, 0, 0, 0, 0};
    for (int i = blockIdx.x * blockDim.x + threadIdx.x; i < NN; i += RB * T) {
        float nn = NRMF[i + off];
        float p1 = nn * S1F[i + off], p2 = nn * S2F[i + off];
        acc[0] += p1; acc[1] += p2;
        acc[2] += (double)p1 * p1; acc[3] += (double)p2 * p2; acc[4] += (double)p1 * p2;
    }
    block_reduce_add<5>(acc, g_stats[g]);
}

__global__ void k_coef1(int g, const float* __restrict__ W_init, const float* __restrict__ b_init,
                        const float* __restrict__ Wg, const float* __restrict__ bg,
                        const float* __restrict__ Wt1, const float* __restrict__ g1,
                        const float* __restrict__ b1) {
    if (threadIdx.x != 0) return;
    float xrow[4];
    for (int j = 0; j < 4; j++) {
        float s = b_init[j];
        for (int i = 0; i < 12; i++) s += W_init[i * 4 + j];
        xrow[j] = s;
    }
    float hrow[7];
    for (int k = 0; k < 7; k++) {
        float s = bg[k];
        for (int j = 0; j < 4; j++) s += xrow[j] * Wg[j * 7 + k];
        hrow[k] = 1.0f / (1.0f + expf(-s));
    }
    const double inv_n = 1.0 / (double)NN;
    double m1 = g_stats[g][0] * inv_n, m2 = g_stats[g][1] * inv_n;
    double v1 = g_stats[g][2] * inv_n - m1 * m1;
    double v2 = g_stats[g][3] * inv_n - m2 * m2;
    double c12 = g_stats[g][4] * inv_n - m1 * m2;
    for (int j = 0; j < 7; j++) {
        float a = 0.f, b = 0.f, c = 0.f;
        for (int k = 0; k < 7; k++) {
            a += hrow[k] * Wt1[k * 7 + j];
            b += hrow[k] * Wt1[(7 + k) * 7 + j];
            c += hrow[k] * Wt1[(14 + k) * 7 + j];
        }
        double mean = (double)a + m1 * (double)b + m2 * (double)c;
        double var = (double)b * b * v1 + (double)c * c * v2 + 2.0 * (double)b * c * c12;
        double sc = (double)g1[j] / sqrt(var + 1e-5);
        g_coef[g][j]      = (float)(((double)a - mean) * sc + (double)b1[j]);
        g_coef[g][8 + j]  = (float)((double)b * sc);
        g_coef[g][16 + j] = (float)((double)c * sc);
    }
}

// h1s = norm*relu(...) (lane7=0); Q1 row = (0,..,0, norm^2); Q2 row = 0
__global__ void k_h1(int g) {
    __shared__ float cf[21];
    if (threadIdx.x < 21)
        cf[threadIdx.x] = g_coef[g][(threadIdx.x / 7) * 8 + threadIdx.x % 7];
    __syncthreads();
    int i = blockIdx.x * blockDim.x + threadIdx.x;
    if (i >= NN) return;
    i += g * NN;
    float nn = NRMF[i];
    float p1 = nn * S1F[i], p2 = nn * S2F[i];
    float o[7];
#pragma unroll
    for (int j = 0; j < 7; j++)
        o[j] = nn * fmaxf(cf[j] + p1 * cf[7 + j] + p2 * cf[14 + j], 0.f);
    __half2 h01 = __floats2half2_rn(o[0], o[1]);
    __half2 h23 = __floats2half2_rn(o[2], o[3]);
    __half2 h45 = __floats2half2_rn(o[4], o[5]);
    __half2 h67 = __floats2half2_rn(o[6], 0.f);
    H1S[i] = make_uint4(h2u(h01), h2u(h23), h2u(h45), h2u(h67));
    __half2 w2 = __floats2half2_rn(0.f, nn * nn);
    Q1R[i] = make_uint4(0u, 0u, 0u, h2u(w2));   // lane7 = norm^2, survives qscat1 (adds 0)
    Q2R[i] = make_uint4(0u, 0u, 0u, 0u);
}

// STEP1: Q1[dst] += h1s[src] (no math; lane7 of h1s = 0)
// STEP2: Q2[dst] += lane7(Q1[src]) * Q1[src], lane7 masked
template <int STEP>
__global__ void k_qscat(const int* __restrict__ src, const int* __restrict__ dst, int E, int off) {
    const uint4* in = (STEP == 1) ? H1S : Q1R;
    uint4* out = (STEP == 1) ? Q1R : Q2R;
    int base = (blockIdx.x * blockDim.x + threadIdx.x) * 4;
    if (base >= E) return;
    int n = min(4, E - base);
    int ss[4], dd[4];
    if (n == 4) {
        int4 sv = *(const int4*)(src + base);
        int4 dv = *(const int4*)(dst + base);
        ss[0] = sv.x; ss[1] = sv.y; ss[2] = sv.z; ss[3] = sv.w;
        dd[0] = dv.x; dd[1] = dv.y; dd[2] = dv.z; dd[3] = dv.w;
    } else {
        for (int q = 0; q < n; q++) { ss[q] = src[base + q]; dd[q] = dst[base + q]; }
    }
#pragma unroll
    for (int q = 0; q < 4; q++) {
        if (q >= n) break;
        uint4 r = __ldg(in + ss[q] + off);
        if (STEP == 2) {
            __half2 p01 = *(__half2*)&r.x, p23 = *(__half2*)&r.y;
            __half2 p45 = *(__half2*)&r.z, p67 = *(__half2*)&r.w;
            __half2 wv = __half2half2(__high2half(p67));   // norm^2 of src
            r.x = h2u(__hmul2(p01, wv));
            r.y = h2u(__hmul2(p23, wv));
            r.z = h2u(__hmul2(p45, wv));
            r.w = h2u(__hmul2(p67, wv)) & 0x0000FFFFu;     // zero lane7
        }
        red_add_v4h2((__half*)(out + dd[q] + off), r);
    }
}

__global__ void k_passF(int g, const float* __restrict__ Wt2) {
    __shared__ float w[147];
    __shared__ float cf[21];
    for (int k = threadIdx.x; k < 147; k += blockDim.x) w[k] = Wt2[k];
    if (threadIdx.x < 21)
        cf[threadIdx.x] = g_coef[g][(threadIdx.x / 7) * 8 + threadIdx.x % 7];
    __syncthreads();
    int off = g * NN;
    double acc[14];
#pragma unroll
    for (int k = 0; k < 14; k++) acc[k] = 0.0;
    for (int i = blockIdx.x * blockDim.x + threadIdx.x; i < NN; i += RB * T) {
        float nn = NRMF[i + off];
        float p1 = nn * S1F[i + off], p2 = nn * S2F[i + off];
        uint4 ar = Q1R[i + off], br = Q2R[i + off];
        float v[21];
#pragma unroll
        for (int j = 0; j < 7; j++)
            v[j] = fmaxf(cf[j] + p1 * cf[7 + j] + p2 * cf[14 + j], 0.f);
        {
            float2 t;
            t = __half22float2(*(__half2*)&ar.x); v[7] = nn * t.x; v[8] = nn * t.y;
            t = __half22float2(*(__half2*)&ar.y); v[9] = nn * t.x; v[10] = nn * t.y;
            t = __half22float2(*(__half2*)&ar.z); v[11] = nn * t.x; v[12] = nn * t.y;
            t = __half22float2(*(__half2*)&ar.w); v[13] = nn * t.x;
            t = __half22float2(*(__half2*)&br.x); v[14] = nn * t.x; v[15] = nn * t.y;
            t = __half22float2(*(__half2*)&br.y); v[16] = nn * t.x; v[17] = nn * t.y;
            t = __half22float2(*(__half2*)&br.z); v[18] = nn * t.x; v[19] = nn * t.y;
            t = __half22float2(*(__half2*)&br.w); v[20] = nn * t.x;
        }
        float xr[7];
#pragma unroll
        for (int j = 0; j < 7; j++) {
            float s = 0.f;
#pragma unroll
            for (int k = 0; k < 21; k++) s += v[k] * w[k * 7 + j];
            xr[j] = s;
        }
        __half2 x01 = __floats2half2_rn(xr[0], xr[1]);
        __half2 x23 = __floats2half2_rn(xr[2], xr[3]);
        __half2 x45 = __floats2half2_rn(xr[4], xr[5]);
        __half2 x67 = __floats2half2_rn(xr[6], 0.f);
        X2R[i + off] = make_uint4(h2u(x01), h2u(x23), h2u(x45), h2u(x67));
#pragma unroll
        for (int j = 0; j < 7; j++) {
            acc[j] += xr[j];
            acc[7 + j] += (double)xr[j] * xr[j];
        }
    }
    block_reduce_add<14>(acc, g_stats[g] + 5);
}

__global__ void k_coef2(int g, const float* __restrict__ g2, const float* __restrict__ b2) {
    if (threadIdx.x != 0) return;
    const double inv_n = 1.0 / (double)NN;
    for (int j = 0; j < 7; j++) {
        double mean = g_stats[g][5 + j] * inv_n;
        double var = g_stats[g][12 + j] * inv_n - mean * mean;
        double sc = (double)g2[j] / sqrt(var + 1e-5);
        g_coef[g][24 + j] = (float)sc;
        g_coef[g][32 + j] = (float)((double)b2[j] - mean * sc);
    }
}

__global__ void k_passG(int g) {
    __shared__ float sc[7], sh[7];
    if (threadIdx.x < 14) {
        int j = threadIdx.x;
        if (j < 7) sc[j] = g_coef[g][24 + j];
        else sh[j - 7] = g_coef[g][32 + j - 7];
    }
    __syncthreads();
    int off = g * NN;
    double acc[7] = {0, 0, 0, 0, 0, 0, 0};
    for (int i = blockIdx.x * blockDim.x + threadIdx.x; i < NN; i += RB * T) {
        uint4 xr = X2R[i + off];
        float v[7];
        float2 t;
        t = __half22float2(*(__half2*)&xr.x); v[0] = t.x; v[1] = t.y;
        t = __half22float2(*(__half2*)&xr.y); v[2] = t.x; v[3] = t.y;
        t = __half22float2(*(__half2*)&xr.z); v[4] = t.x; v[5] = t.y;
        t = __half22float2(*(__half2*)&xr.w); v[6] = t.x;
#pragma unroll
        for (int j = 0; j < 7; j++)
            acc[j] += fmaxf(v[j] * sc[j] + sh[j], 0.f);
    }
    block_reduce_add<7>(acc, g_stats[g] + 19);
}

__global__ void k_fin(const float* __restrict__ Wd, const float* __restrict__ bd,
                      const float* __restrict__ Ws0, const float* __restrict__ bs0,
                      const float* __restrict__ Ws1, const float* __restrict__ bs1,
                      const float* __restrict__ Ws2, const float* __restrict__ bs2,
                      const float* __restrict__ Ws3, const float* __restrict__ bs3,
                      const float* __restrict__ Wsim, const float* __restrict__ bsim,
                      float* __restrict__ out) {
    if (threadIdx.x != 0) return;
    const double inv_n = 1.0 / (double)NN;
    float h[22];
    for (int g = 0; g < 2; g++)
        for (int m = 0; m < 11; m++) {
            double s = (double)bd[m];
            for (int j = 0; j < 7; j++)
                s += (g_stats[g][19 + j] * inv_n) * (double)Wd[j * 11 + m];
            h[g * 11 + m] = (float)s;
        }
    float t[7], u[7];
    for (int j = 0; j < 7; j++) {
        float s = bs0[j];
        for (int k = 0; k < 22; k++) s += h[k] * Ws0[k * 7 + j];
        t[j] = s;
    }
    for (int j = 0; j < 7; j++) {
        float s = bs1[j];
        for (int k = 0; k < 7; k++) s += t[k] * Ws1[k * 7 + j];
        u[j] = fmaxf(s, 0.f);
    }
    for (int j = 0; j < 7; j++) {
        float s = bs2[j];
        for (int k = 0; k < 7; k++) s += u[k] * Ws2[k * 7 + j];
        t[j] = fmaxf(s, 0.f);
    }
    for (int j = 0; j < 7; j++) {
        float s = bs3[j];
        for (int k = 0; k < 7; k++) s += t[k] * Ws3[k * 7 + j];
        u[j] = fmaxf(s, 0.f);
    }
    for (int m = 0; m < 12; m++) {
        float s = bsim[m];
        for (int j = 0; j < 7; j++) s += u[j] * Wsim[j * 12 + m];
        out[m] = 1.0f / (1.0f + expf(-s));
    }
}

// ---------------- launch ----------------
extern "C" void kernel_launch(void* const* d_in, const int* in_sizes, int n_in,
                              void* d_out, int out_size) {
    const int* src0 = (const int*)d_in[0];
    const int* dst0 = (const int*)d_in[1];
    const int* src1 = (const int*)d_in[2];
    const int* dst1 = (const int*)d_in[3];
    const float* W_init = (const float*)d_in[5];
    const float* b_init = (const float*)d_in[6];
    const float* Wg  = (const float*)d_in[7];
    const float* bg  = (const float*)d_in[8];
    const float* Wt1 = (const float*)d_in[9];
    const float* g1  = (const float*)d_in[10];
    const float* b1  = (const float*)d_in[11];
    const float* Wt2 = (const float*)d_in[12];
    const float* g2  = (const float*)d_in[13];
    const float* b2  = (const float*)d_in[14];
    const float* Wd  = (const float*)d_in[15];
    const float* bd  = (const float*)d_in[16];
    const float* Ws0 = (const float*)d_in[17];
    const float* bs0 = (const float*)d_in[18];
    const float* Ws1 = (const float*)d_in[19];
    const float* bs1 = (const float*)d_in[20];
    const float* Ws2 = (const float*)d_in[21];
    const float* bs2 = (const float*)d_in[22];
    const float* Ws3 = (const float*)d_in[23];
    const float* bs3 = (const float*)d_in[24];
    const float* Wsim = (const float*)d_in[25];
    const float* bsim = (const float*)d_in[26];

    static cudaStream_t s1 = 0;
    static cudaEvent_t ev_fork = 0, ev_stag = 0, ev_join = 0;
    static int inited = 0;
    if (!inited) {
        if (cudaStreamCreateWithFlags(&s1, cudaStreamNonBlocking) != cudaSuccess) s1 = 0;
        cudaEventCreateWithFlags(&ev_fork, cudaEventDisableTiming);
        cudaEventCreateWithFlags(&ev_stag, cudaEventDisableTiming);
        cudaEventCreateWithFlags(&ev_join, cudaEventDisableTiming);
        inited = 1;
    }

    const int E0 = in_sizes[0];
    const int E1 = in_sizes[2];
    const int eb0 = (E0 + T * 4 - 1) / (T * 4);
    const int eb1 = (E1 + T * 4 - 1) / (T * 4);
    const int nbg = (NN + T - 1) / T;

    k_zero<<<592, T>>>();
    cudaEventRecord(ev_fork, 0);

    // ---- graph 0 on default stream ----
    k_deg<<<eb0, T>>>(dst0, E0, 0);
    cudaEventRecord(ev_stag, 0);
    k_norm<<<nbg, T>>>(0);
    k_p1<<<eb0, T>>>(src0, dst0, E0, 0);
    k_pack<<<nbg, T>>>(0);
    k_p2<<<eb0, T>>>(src0, dst0, E0, 0);
    k_stats1<<<RB, T>>>(0);
    k_coef1<<<1, 32>>>(0, W_init, b_init, Wg, bg, Wt1, g1, b1);
    k_h1<<<nbg, T>>>(0);
    k_qscat<1><<<eb0, T>>>(src0, dst0, E0, 0);
    k_qscat<2><<<eb0, T>>>(src0, dst0, E0, 0);
    k_passF<<<RB, T>>>(0, Wt2);
    k_coef2<<<1, 32>>>(0, g2, b2);
    k_passG<<<RB, T>>>(0);

    // ---- graph 1 on second stream (staggered by one edge pass) ----
    cudaStreamWaitEvent(s1, ev_fork, 0);
    cudaStreamWaitEvent(s1, ev_stag, 0);
    k_deg<<<eb1, T, 0, s1>>>(dst1, E1, NN);
    k_norm<<<nbg, T, 0, s1>>>(NN);
    k_p1<<<eb1, T, 0, s1>>>(src1, dst1, E1, NN);
    k_pack<<<nbg, T, 0, s1>>>(NN);
    k_p2<<<eb1, T, 0, s1>>>(src1, dst1, E1, NN);
    k_stats1<<<RB, T, 0, s1>>>(1);
    k_coef1<<<1, 32, 0, s1>>>(1, W_init, b_init, Wg, bg, Wt1, g1, b1);
    k_h1<<<nbg, T, 0, s1>>>(1);
    k_qscat<1><<<eb1, T, 0, s1>>>(src1, dst1, E1, NN);
    k_qscat<2><<<eb1, T, 0, s1>>>(src1, dst1, E1, NN);
    k_passF<<<RB, T, 0, s1>>>(1, Wt2);
    k_coef2<<<1, 32, 0, s1>>>(1, g2, b2);
    k_passG<<<RB, T, 0, s1>>>(1);
    cudaEventRecord(ev_join, s1);

    // ---- join + head ----
    cudaStreamWaitEvent(0, ev_join, 0);
    k_fin<<<1, 32>>>(Wd, bd, Ws0, bs0, Ws1, bs1, Ws2, bs2, Ws3, bs3, Wsim, bsim, (float*)d_out);
}